// round 12
// baseline (speedup 1.0000x reference)
#include <cuda_runtime.h>
#include <cuda_fp16.h>
#include <cstdint>
#include <cstddef>

// ---------------------------------------------------------------------------
// Problem constants
// ---------------------------------------------------------------------------
#define OUT_N  11008
#define IN_K   4096
#define NGRPS  (OUT_N * IN_K / 16)   // 2818048
#define M_ROWS 4096                  // 2 * 2048

// Scratch (allocation-free rule: __device__ globals)
__device__ __half g_w[(size_t)OUT_N * IN_K];   // dequantized W, [N, K] K-major
__device__ __half g_x[(size_t)M_ROWS * IN_K];  // fp16 x,        [M, K] K-major

// ---------------------------------------------------------------------------
// Helpers (base sm_103 PTX only: cp.async + mma.sync)
// ---------------------------------------------------------------------------
__device__ __forceinline__ uint32_t smem_u32(const void* p) {
    uint32_t a;
    asm("{ .reg .u64 t; cvta.to.shared.u64 t, %1; cvt.u32.u64 %0, t; }"
        : "=r"(a) : "l"(p));
    return a;
}

__device__ __forceinline__ void cp_async16(uint32_t dst, const void* src) {
    asm volatile("cp.async.cg.shared.global [%0], [%1], 16;"
                 :: "r"(dst), "l"(src) : "memory");
}
#define CP_COMMIT() asm volatile("cp.async.commit_group;" ::: "memory")
#define CP_WAIT(n)  asm volatile("cp.async.wait_group %0;" :: "n"(n) : "memory")

__device__ __forceinline__ void mma_16816(float* c, const uint32_t* a,
                                          const uint32_t* b) {
    asm volatile(
        "mma.sync.aligned.m16n8k16.row.col.f32.f16.f16.f32 "
        "{%0,%1,%2,%3}, {%4,%5,%6,%7}, {%8,%9}, {%0,%1,%2,%3};"
        : "+f"(c[0]), "+f"(c[1]), "+f"(c[2]), "+f"(c[3])
        : "r"(a[0]), "r"(a[1]), "r"(a[2]), "r"(a[3]), "r"(b[0]), "r"(b[1]));
}

// ---------------------------------------------------------------------------
// Kernel 1: dequantize packed 4-bit weights -> fp16 [N, K]
//   group g: row = g/256, k = (g%256)*16 .. +15; int32 code word (0..255):
//   low nibble -> even position, high nibble -> odd position.
//   *** weight_norm is FLOAT32 (harness upconverts jax f16 -> f32). ***
// ---------------------------------------------------------------------------
__global__ void dequant_w_kernel(const int* __restrict__ q,
                                 const float* __restrict__ norm) {
    int g = blockIdx.x * blockDim.x + threadIdx.x;
    if (g >= NGRPS) return;
    const int4* qp = (const int4*)q + (size_t)g * 2;
    int4 a = qp[0], b = qp[1];
    float n = norm[g];
    float s = n * (2.0f / 15.0f);
    int v[8] = {a.x, a.y, a.z, a.w, b.x, b.y, b.z, b.w};
    __half2 h[8];
#pragma unroll
    for (int j = 0; j < 8; j++) {
        float lo = (float)(v[j] & 15)        * s - n;   // even position 2j
        float hi = (float)((v[j] >> 4) & 15) * s - n;   // odd position 2j+1
        h[j] = __floats2half2_rn(lo, hi);
    }
    uint4* dst = (uint4*)(g_w + (size_t)g * 16);
    dst[0] = *(uint4*)&h[0];
    dst[1] = *(uint4*)&h[4];
}

// ---------------------------------------------------------------------------
// Kernel 2: x fp32 -> fp16
// ---------------------------------------------------------------------------
__global__ void convert_x_kernel(const float* __restrict__ x, int n4) {
    int i = blockIdx.x * blockDim.x + threadIdx.x;
    if (i >= n4) return;
    float4 v = ((const float4*)x)[i];
    __half2* dst = (__half2*)g_x;
    dst[2 * i]     = __floats2half2_rn(v.x, v.y);
    dst[2 * i + 1] = __floats2half2_rn(v.z, v.w);
}

// ---------------------------------------------------------------------------
// Kernel 3: fp16 HMMA GEMM, fp32 accumulation. Padded smem rows (40 halves =
// 80 B) -> conflict-free direct LDS fragment loads per the PTX ISA m16n8k16
// fragment tables.  C[m, n] = sum_k g_x[m,k] * g_w[n,k] + bias[n]
//   (GEMM structure cross-validated: bit-consistent with two independent
//    implementations in R7-R9.)
// ---------------------------------------------------------------------------
constexpr int BM = 128, BN = 128, BK = 32, NSTAGE = 4;
constexpr int ROWB  = 80;                 // padded row bytes (40 halves)
constexpr int ROWW  = 20;                 // padded row in 4B words
constexpr int ATILE = BM * ROWB;          // 10240 B
constexpr int STAGE = 2 * ATILE;          // 20480 B (A then B)
constexpr int SMEM_OFF = 1024;
constexpr int SMEM_TOTAL = SMEM_OFF + NSTAGE * STAGE;   // 82944
constexpr int KCHUNKS = IN_K / BK;        // 128

__global__ void __launch_bounds__(256, 2)
gemm_f16_kernel(const float* __restrict__ bias, float* __restrict__ out) {
    extern __shared__ char smem[];
    uint32_t sb = smem_u32(smem);
    int tid = threadIdx.x, wid = tid >> 5, lid = tid & 31;
    int mBase = blockIdx.x * BM;
    int nBase = blockIdx.y * BN;

    float* biasS = (float*)smem;
    if (tid < BN) biasS[tid] = bias[nBase + tid];

    const char* gA = (const char*)(g_x + (size_t)mBase * IN_K);
    const char* gB = (const char*)(g_w + (size_t)nBase * IN_K);

    // 512 x 16B chunks each for A and B per stage; 256 threads x 2 each
    auto load_stage = [&](int chunk, int s) {
        uint32_t base = sb + SMEM_OFF + s * STAGE;
        const char* srcA = gA + chunk * 64;       // 32 halves = 64 B along K
        const char* srcB = gB + chunk * 64;
#pragma unroll
        for (int i = 0; i < 2; i++) {
            int idx = tid + i * 256;
            int r = idx >> 2, j = idx & 3;        // row 0..127, 16B chunk 0..3
            cp_async16(base + r * ROWB + j * 16,
                       srcA + (size_t)r * (IN_K * 2) + j * 16);
        }
        uint32_t bbase = base + ATILE;
#pragma unroll
        for (int i = 0; i < 2; i++) {
            int idx = tid + i * 256;
            int r = idx >> 2, j = idx & 3;
            cp_async16(bbase + r * ROWB + j * 16,
                       srcB + (size_t)r * (IN_K * 2) + j * 16);
        }
    };

    // Prologue: fill NSTAGE-1 stages
#pragma unroll
    for (int c = 0; c < NSTAGE - 1; c++) { load_stage(c, c); CP_COMMIT(); }

    int wm = (wid & 3) * 32;     // warp m offset (4 rows of warps)
    int wn = (wid >> 2) * 64;    // warp n offset (2 cols of warps)
    int gid = lid >> 2, tig = lid & 3;   // groupID, threadID-in-group

    float acc[2][8][4];
#pragma unroll
    for (int mi = 0; mi < 2; mi++)
#pragma unroll
        for (int ni = 0; ni < 8; ni++)
#pragma unroll
            for (int j = 0; j < 4; j++) acc[mi][ni][j] = 0.0f;

#pragma unroll 1
    for (int c = 0; c < KCHUNKS; c++) {
        int s = c & (NSTAGE - 1);
        CP_WAIT(2);            // oldest group (stage s) complete
        __syncthreads();
        if (c + NSTAGE - 1 < KCHUNKS)
            load_stage(c + NSTAGE - 1, (c + NSTAGE - 1) & (NSTAGE - 1));
        CP_COMMIT();           // empty group in tail keeps counting consistent

        const uint32_t* sA = (const uint32_t*)(smem + SMEM_OFF + s * STAGE);
        const uint32_t* sB = (const uint32_t*)(smem + SMEM_OFF + s * STAGE + ATILE);

#pragma unroll
        for (int ks = 0; ks < 2; ks++) {
            // A fragments (PTX ISA m16n8k16):
            //  a0: row=gid, k=2tig,+1 | a1: row=gid+8 | a2: k+8 | a3: both
            uint32_t a[2][4];
#pragma unroll
            for (int mi = 0; mi < 2; mi++) {
                int w = (wm + mi * 16 + gid) * ROWW + ks * 8 + tig;
                a[mi][0] = sA[w];
                a[mi][1] = sA[w + 8 * ROWW];
                a[mi][2] = sA[w + 4];
                a[mi][3] = sA[w + 8 * ROWW + 4];
            }
            // B fragments: b[g][0..1]: n = g*16+gid, k=2tig,+1 / +8
            //              b[g][2..3]: n = g*16+8+gid
            uint32_t b[4][4];
#pragma unroll
            for (int g = 0; g < 4; g++) {
                int w = (wn + g * 16 + gid) * ROWW + ks * 8 + tig;
                b[g][0] = sB[w];
                b[g][1] = sB[w + 4];
                b[g][2] = sB[w + 8 * ROWW];
                b[g][3] = sB[w + 8 * ROWW + 4];
            }
#pragma unroll
            for (int mi = 0; mi < 2; mi++)
#pragma unroll
                for (int ni = 0; ni < 8; ni++)
                    mma_16816(acc[mi][ni], a[mi], &b[ni >> 1][(ni & 1) * 2]);
        }
    }

    // Epilogue: c0,c1 -> (row gid, cols 2tig,+1); c2,c3 -> row gid+8
#pragma unroll
    for (int mi = 0; mi < 2; mi++) {
        int r0 = mBase + wm + mi * 16 + gid;
#pragma unroll
        for (int ni = 0; ni < 8; ni++) {
            int col = wn + ni * 8 + tig * 2;
            float b0 = biasS[col], b1 = biasS[col + 1];
            float2 v0 = {acc[mi][ni][0] + b0, acc[mi][ni][1] + b1};
            float2 v1 = {acc[mi][ni][2] + b0, acc[mi][ni][3] + b1};
            *(float2*)(out + (size_t)r0 * OUT_N + nBase + col) = v0;
            *(float2*)(out + (size_t)(r0 + 8) * OUT_N + nBase + col) = v1;
        }
    }
}

// ---------------------------------------------------------------------------
// Entry point — identify inputs by element count (robust to metadata order):
//   x: 16777216 (f32), weight_q4: 22544384 (i32),
//   weight_norm: 2818048 (FLOAT32 — f16 upconverted), bias: 11008 (f32)
// ---------------------------------------------------------------------------
extern "C" void kernel_launch(void* const* d_in, const int* in_sizes, int n_in,
                              void* d_out, int out_size) {
    const float* x    = (const float*)d_in[0];
    const int*   wq   = (const int*)d_in[1];
    const float* wn   = (const float*)d_in[2];
    const float* bias = (const float*)d_in[3];
    for (int i = 0; i < n_in; i++) {
        switch (in_sizes[i]) {
            case 16777216: x    = (const float*)d_in[i]; break;
            case 22544384: wq   = (const int*)d_in[i];   break;
            case 2818048:  wn   = (const float*)d_in[i]; break;
            case 11008:    bias = (const float*)d_in[i]; break;
            default: break;
        }
    }
    float* out = (float*)d_out;

    dequant_w_kernel<<<(NGRPS + 255) / 256, 256>>>(wq, wn);

    int n4 = (M_ROWS * IN_K) / 4;
    convert_x_kernel<<<(n4 + 255) / 256, 256>>>(x, n4);

    cudaFuncSetAttribute(gemm_f16_kernel,
                         cudaFuncAttributeMaxDynamicSharedMemorySize, SMEM_TOTAL);
    dim3 grid(M_ROWS / BM, OUT_N / BN);
    gemm_f16_kernel<<<grid, 256, SMEM_TOTAL>>>(bias, out);
}

// round 13
// speedup vs baseline: 2.3538x; 2.3538x over previous
#include <cuda_runtime.h>
#include <cuda_fp16.h>
#include <cstdint>
#include <cstddef>

// ---------------------------------------------------------------------------
// Problem constants
// ---------------------------------------------------------------------------
#define OUT_N  11008
#define IN_K   4096
#define NGRPS  (OUT_N * IN_K / 16)   // 2818048
#define M_ROWS 4096                  // 2 * 2048

// Scratch (allocation-free rule: __device__ globals)
__device__ __half g_w[(size_t)OUT_N * IN_K];   // dequantized W, [N, K] K-major
__device__ __half g_x[(size_t)M_ROWS * IN_K];  // fp16 x,        [M, K] K-major

// ---------------------------------------------------------------------------
// Helpers (base sm_103 PTX only: cp.async, ldmatrix, mma.sync)
// ---------------------------------------------------------------------------
__device__ __forceinline__ uint32_t smem_u32(const void* p) {
    uint32_t a;
    asm("{ .reg .u64 t; cvta.to.shared.u64 t, %1; cvt.u32.u64 %0, t; }"
        : "=r"(a) : "l"(p));
    return a;
}

__device__ __forceinline__ void cp_async16(uint32_t dst, const void* src) {
    asm volatile("cp.async.cg.shared.global [%0], [%1], 16;"
                 :: "r"(dst), "l"(src) : "memory");
}
#define CP_COMMIT() asm volatile("cp.async.commit_group;" ::: "memory")
#define CP_WAIT(n)  asm volatile("cp.async.wait_group %0;" :: "n"(n) : "memory")

// memory clobber load-bearing: orders the smem read vs wait/barrier
__device__ __forceinline__ void ldsm_x4(uint32_t* r, uint32_t addr) {
    asm volatile("ldmatrix.sync.aligned.m8n8.x4.shared.b16 {%0,%1,%2,%3}, [%4];"
                 : "=r"(r[0]), "=r"(r[1]), "=r"(r[2]), "=r"(r[3])
                 : "r"(addr) : "memory");
}

__device__ __forceinline__ void mma_16816(float* c, const uint32_t* a,
                                          const uint32_t* b) {
    asm volatile(
        "mma.sync.aligned.m16n8k16.row.col.f32.f16.f16.f32 "
        "{%0,%1,%2,%3}, {%4,%5,%6,%7}, {%8,%9}, {%0,%1,%2,%3};"
        : "+f"(c[0]), "+f"(c[1]), "+f"(c[2]), "+f"(c[3])
        : "r"(a[0]), "r"(a[1]), "r"(a[2]), "r"(a[3]), "r"(b[0]), "r"(b[1]));
}

// SW128 swizzle for 128-byte rows (bijective; same map on write & read)
__device__ __forceinline__ uint32_t swz128(uint32_t off) {
    return off ^ ((off >> 3) & 0x70);
}

// ---------------------------------------------------------------------------
// Kernel 1: dequantize packed 4-bit weights -> fp16 [N, K]
//   weight_norm is FLOAT32 (harness upconverts jax f16 -> f32)  [R12-proven]
// ---------------------------------------------------------------------------
__global__ void dequant_w_kernel(const int* __restrict__ q,
                                 const float* __restrict__ norm) {
    int g = blockIdx.x * blockDim.x + threadIdx.x;
    if (g >= NGRPS) return;
    const int4* qp = (const int4*)q + (size_t)g * 2;
    int4 a = qp[0], b = qp[1];
    float n = norm[g];
    float s = n * (2.0f / 15.0f);
    int v[8] = {a.x, a.y, a.z, a.w, b.x, b.y, b.z, b.w};
    __half2 h[8];
#pragma unroll
    for (int j = 0; j < 8; j++) {
        float lo = (float)(v[j] & 15)        * s - n;   // even position 2j
        float hi = (float)((v[j] >> 4) & 15) * s - n;   // odd position 2j+1
        h[j] = __floats2half2_rn(lo, hi);
    }
    uint4* dst = (uint4*)(g_w + (size_t)g * 16);
    dst[0] = *(uint4*)&h[0];
    dst[1] = *(uint4*)&h[4];
}

// ---------------------------------------------------------------------------
// Kernel 2: x fp32 -> fp16
// ---------------------------------------------------------------------------
__global__ void convert_x_kernel(const float* __restrict__ x, int n4) {
    int i = blockIdx.x * blockDim.x + threadIdx.x;
    if (i >= n4) return;
    float4 v = ((const float4*)x)[i];
    __half2* dst = (__half2*)g_x;
    dst[2 * i]     = __floats2half2_rn(v.x, v.y);
    dst[2 * i + 1] = __floats2half2_rn(v.z, v.w);
}

// ---------------------------------------------------------------------------
// Kernel 3: fp16 HMMA GEMM, fp32 accumulation.
//   C[m, n] = sum_k g_x[m,k] * g_w[n,k] + bias[n]
//   CTA 128x128, BK=64 (128B rows, SW128), ldmatrix fragments, 3-stage
//   cp.async pipeline, 2 CTAs/SM.
// ---------------------------------------------------------------------------
constexpr int BM = 128, BN = 128, BK = 64, NSTAGE = 3;
constexpr int ROWB  = 128;                 // 64 halves = 128 B per row
constexpr int ATILE = BM * ROWB;           // 16384 B
constexpr int STAGE = 2 * ATILE;           // 32768 B (A then B)
constexpr int SMEM_OFF = 1024;
constexpr int SMEM_TOTAL = SMEM_OFF + NSTAGE * STAGE;   // 99328
constexpr int KCHUNKS = IN_K / BK;         // 64

__global__ void __launch_bounds__(256, 2)
gemm_f16_kernel(const float* __restrict__ bias, float* __restrict__ out) {
    extern __shared__ char smem[];
    uint32_t sb = smem_u32(smem);
    int tid = threadIdx.x, wid = tid >> 5, lid = tid & 31;
    int mBase = blockIdx.x * BM;
    int nBase = blockIdx.y * BN;

    float* biasS = (float*)smem;
    if (tid < BN) biasS[tid] = bias[nBase + tid];

    const char* gA = (const char*)(g_x + (size_t)mBase * IN_K);
    const char* gB = (const char*)(g_w + (size_t)nBase * IN_K);

    // Per stage: A = 128 rows x 8 x 16B chunks, B same; 256 threads x 4 each
    auto load_stage = [&](int chunk, int s) {
        uint32_t base = sb + SMEM_OFF + s * STAGE;
        const char* srcA = gA + chunk * 128;   // 64 halves = 128 B along K
        const char* srcB = gB + chunk * 128;
#pragma unroll
        for (int i = 0; i < 4; i++) {
            int idx = tid + i * 256;
            int r = idx >> 3, j = idx & 7;     // row 0..127, 16B chunk 0..7
            cp_async16(base + swz128(r * 128 + j * 16),
                       srcA + (size_t)r * (IN_K * 2) + j * 16);
        }
        uint32_t bbase = base + ATILE;
#pragma unroll
        for (int i = 0; i < 4; i++) {
            int idx = tid + i * 256;
            int r = idx >> 3, j = idx & 7;
            cp_async16(bbase + swz128(r * 128 + j * 16),
                       srcB + (size_t)r * (IN_K * 2) + j * 16);
        }
    };

    // Prologue: fill NSTAGE-1 stages
#pragma unroll
    for (int c = 0; c < NSTAGE - 1; c++) { load_stage(c, c); CP_COMMIT(); }

    int wm = (wid & 3) * 32;     // warp m offset (4 rows of warps)
    int wn = (wid >> 2) * 64;    // warp n offset (2 cols of warps)
    int gid = lid >> 2, tig = lid & 3;

    // ldmatrix lane coords (validated mapping, R2-structure):
    int aRow = lid & 15;              // A: rows m0..15, lanes 16-31 -> k+8 half
    int aK16 = lid >> 4;
    int bRow = ((lid >> 4) & 1) * 8 + (lid & 7);   // B: n-halves / k-halves
    int bK16 = (lid >> 3) & 1;

    float acc[2][8][4];
#pragma unroll
    for (int mi = 0; mi < 2; mi++)
#pragma unroll
        for (int ni = 0; ni < 8; ni++)
#pragma unroll
            for (int j = 0; j < 4; j++) acc[mi][ni][j] = 0.0f;

#pragma unroll 1
    for (int c = 0; c < KCHUNKS; c++) {
        int s = c % NSTAGE;
        CP_WAIT(1);            // oldest pending group (stage s) complete
        __syncthreads();
        if (c + NSTAGE - 1 < KCHUNKS)
            load_stage(c + NSTAGE - 1, (c + NSTAGE - 1) % NSTAGE);
        CP_COMMIT();           // empty group in tail keeps counting consistent

        uint32_t aBase = sb + SMEM_OFF + s * STAGE;
        uint32_t bBase = aBase + ATILE;

#pragma unroll
        for (int ks = 0; ks < 4; ks++) {       // four k16 steps per chunk
            uint32_t a[2][4], b[4][4];
#pragma unroll
            for (int mi = 0; mi < 2; mi++) {
                int m = wm + mi * 16 + aRow;
                ldsm_x4(a[mi], aBase + swz128(m * 128 + ks * 32 + aK16 * 16));
            }
#pragma unroll
            for (int g = 0; g < 4; g++) {
                int n = wn + g * 16 + bRow;
                ldsm_x4(b[g], bBase + swz128(n * 128 + ks * 32 + bK16 * 16));
            }
#pragma unroll
            for (int mi = 0; mi < 2; mi++)
#pragma unroll
                for (int ni = 0; ni < 8; ni++)
                    mma_16816(acc[mi][ni], a[mi], &b[ni >> 1][(ni & 1) * 2]);
        }
    }

    // Epilogue: c0,c1 -> (row gid, cols 2tig,+1); c2,c3 -> row gid+8
#pragma unroll
    for (int mi = 0; mi < 2; mi++) {
        int r0 = mBase + wm + mi * 16 + gid;
#pragma unroll
        for (int ni = 0; ni < 8; ni++) {
            int col = wn + ni * 8 + tig * 2;
            float b0 = biasS[col], b1 = biasS[col + 1];
            float2 v0 = {acc[mi][ni][0] + b0, acc[mi][ni][1] + b1};
            float2 v1 = {acc[mi][ni][2] + b0, acc[mi][ni][3] + b1};
            *(float2*)(out + (size_t)r0 * OUT_N + nBase + col) = v0;
            *(float2*)(out + (size_t)(r0 + 8) * OUT_N + nBase + col) = v1;
        }
    }
}

// ---------------------------------------------------------------------------
// Entry point — identify inputs by element count (robust to metadata order):
//   x: 16777216 (f32), weight_q4: 22544384 (i32),
//   weight_norm: 2818048 (f32), bias: 11008 (f32)
// ---------------------------------------------------------------------------
extern "C" void kernel_launch(void* const* d_in, const int* in_sizes, int n_in,
                              void* d_out, int out_size) {
    const float* x    = (const float*)d_in[0];
    const int*   wq   = (const int*)d_in[1];
    const float* wn   = (const float*)d_in[2];
    const float* bias = (const float*)d_in[3];
    for (int i = 0; i < n_in; i++) {
        switch (in_sizes[i]) {
            case 16777216: x    = (const float*)d_in[i]; break;
            case 22544384: wq   = (const int*)d_in[i];   break;
            case 2818048:  wn   = (const float*)d_in[i]; break;
            case 11008:    bias = (const float*)d_in[i]; break;
            default: break;
        }
    }
    float* out = (float*)d_out;

    dequant_w_kernel<<<(NGRPS + 255) / 256, 256>>>(wq, wn);

    int n4 = (M_ROWS * IN_K) / 4;
    convert_x_kernel<<<(n4 + 255) / 256, 256>>>(x, n4);

    cudaFuncSetAttribute(gemm_f16_kernel,
                         cudaFuncAttributeMaxDynamicSharedMemorySize, SMEM_TOTAL);
    dim3 grid(M_ROWS / BM, OUT_N / BN);
    gemm_f16_kernel<<<grid, 256, SMEM_TOTAL>>>(bias, out);
}